// round 7
// baseline (speedup 1.0000x reference)
#include <cuda_runtime.h>
#include <cuda_bf16.h>
#include <cstdint>
#include <cstddef>

#define BN_EPS 1e-5f
#define SROW 40

// ======================= static scratch (no allocs) =======================
__device__ float g_acc [30000 * 512];
__device__ float g_bufA[30000 * 512];
__device__ float g_bufB[30000 * 512];
__device__ float g_wt  [13450240];      // transposed tf32 weights pool
__device__ float g_sum [512];
__device__ float g_sq  [512];
__device__ float g_scale[512];
__device__ float g_shift[512];

// ======================= helpers =========================================
__device__ __forceinline__ float to_tf32(float x) {
    float y;
    asm("cvt.rna.tf32.f32 %0, %1;" : "=f"(y) : "f"(x));
    return y;
}
__device__ __forceinline__ void mma_tf32(float* d, const uint32_t* a, const uint32_t* b) {
    asm volatile(
        "mma.sync.aligned.m16n8k8.row.col.f32.tf32.tf32.f32 "
        "{%0,%1,%2,%3}, {%4,%5,%6,%7}, {%8,%9}, {%0,%1,%2,%3};"
        : "+f"(d[0]), "+f"(d[1]), "+f"(d[2]), "+f"(d[3])
        : "r"(a[0]), "r"(a[1]), "r"(a[2]), "r"(a[3]), "r"(b[0]), "r"(b[1]));
}
__device__ __forceinline__ void red_add_v2(float* p, float a, float b) {
    asm volatile("red.global.add.v2.f32 [%0], {%1, %2};"
                 :: "l"(p), "f"(a), "f"(b) : "memory");
}

// ======================= tensor-core gather-GEMM-scatter ==================
// CTA: 256 thr (8 warps 2x4), tile 128(M) x 128(N), K-chunks of 32.
// Inputs are PRE-CONVERTED to tf32 (weights in transpose, activations in BN/
// copy kernels) -> inner loop is raw bit movement + MMA only.
// Both A (gathered rows) and B chunks are register-prefetched one chunk ahead
// so the MMA block covers their global-load latency.
__global__ __launch_bounds__(256, 2) void mma_gs_kernel(
    const float* __restrict__ A, const float* __restrict__ WT,
    const int* __restrict__ in_idx, const int* __restrict__ out_idx,
    float* __restrict__ C, int M, int Cin, int Cout)
{
    __shared__ float As[128 * SROW];
    __shared__ float Bs[128 * SROW];
    __shared__ int   rowIdx[128];

    const int tid  = threadIdx.x;
    const int wid  = tid >> 5;
    const int lane = tid & 31;
    const int g8   = lane >> 2;
    const int t4   = lane & 3;

    const int k     = blockIdx.z;
    const int mBase = blockIdx.x * 128;
    const int n0    = blockIdx.y * 128;
    const float* WTk = WT + (size_t)k * Cout * Cin;

    const int warpM = (wid >> 2) * 64;
    const int warpN = (wid & 3) * 32;

    if (tid < 128) {
        int g = mBase + tid;
        int ri = 0;
        if (g < M) ri = in_idx ? in_idx[(size_t)k * M + g] : g;
        rowIdx[tid] = ri;
    }
    __syncthreads();

    // cached per-thread A source pointers (include 4j column offset)
    const float* aptr[4];
#pragma unroll
    for (int s = 0; s < 4; ++s) {
        int gi = tid + s * 256;
        int row = gi >> 3, j = gi & 7;
        aptr[s] = A + (size_t)rowIdx[row] * Cin + 4 * j;
    }

    float d[4][4][4];
#pragma unroll
    for (int mi = 0; mi < 4; mi++)
#pragma unroll
        for (int ni = 0; ni < 4; ni++)
#pragma unroll
            for (int r = 0; r < 4; r++) d[mi][ni][r] = 0.f;

    const int nc = (Cin + 31) >> 5;

    // prologue: prefetch chunk 0 of A and B into registers
    float4 pav[4], pbv[4];
#pragma unroll
    for (int s = 0; s < 4; ++s) {
        int gi = tid + s * 256;
        int row = gi >> 3, j = gi & 7;
        int col = 4 * j;
        pav[s] = make_float4(0.f, 0.f, 0.f, 0.f);
        if (col < Cin) pav[s] = *(const float4*)(aptr[s]);
        pbv[s] = make_float4(0.f, 0.f, 0.f, 0.f);
        if (col < Cin && (n0 + row) < Cout)
            pbv[s] = *(const float4*)(WTk + (size_t)(n0 + row) * Cin + col);
    }

    for (int c = 0; c < nc; ++c) {
        // ---- store prefetched A and B into swizzled smem (raw bits) ----
#pragma unroll
        for (int s = 0; s < 4; ++s) {
            int gi  = tid + s * 256;
            int row = gi >> 3, j = gi & 7;
            int e    = (row << 1) & 6;
            int base = row * SROW + (j >> 1) * 8;
            int o    = j & 1;
            As[base + ((0 + o) ^ e)] = pav[s].x;
            As[base + ((2 + o) ^ e)] = pav[s].y;
            As[base + ((4 + o) ^ e)] = pav[s].z;
            As[base + ((6 + o) ^ e)] = pav[s].w;
            Bs[base + ((0 + o) ^ e)] = pbv[s].x;
            Bs[base + ((2 + o) ^ e)] = pbv[s].y;
            Bs[base + ((4 + o) ^ e)] = pbv[s].z;
            Bs[base + ((6 + o) ^ e)] = pbv[s].w;
        }
        __syncthreads();

        // ---- prefetch chunk c+1 (latency covered by MMA block below) ----
        if (c + 1 < nc) {
            const int c1 = (c + 1) << 5;
#pragma unroll
            for (int s = 0; s < 4; ++s) {
                int gi = tid + s * 256;
                int row = gi >> 3, j = gi & 7;
                int col = c1 + 4 * j;
                pav[s] = make_float4(0.f, 0.f, 0.f, 0.f);
                if (col < Cin) pav[s] = *(const float4*)(aptr[s] + c1);
                pbv[s] = make_float4(0.f, 0.f, 0.f, 0.f);
                if (col < Cin && (n0 + row) < Cout)
                    pbv[s] = *(const float4*)(WTk + (size_t)(n0 + row) * Cin + col);
            }
        }

        // ---- 4 k8 MMA steps, conflict-free LDS.64 fragment loads ----
#pragma unroll
        for (int kk = 0; kk < 4; ++kk) {
            const int kb = kk << 3;
            uint32_t a[4][4];
#pragma unroll
            for (int mi = 0; mi < 4; mi++) {
                int r = warpM + mi * 16 + g8;
                int e = (r << 1) & 6;
                int off = r * SROW + kb + ((2 * t4) ^ e);
                float2 v0 = *(const float2*)&As[off];
                float2 v1 = *(const float2*)&As[off + 8 * SROW];
                a[mi][0] = __float_as_uint(v0.x);
                a[mi][2] = __float_as_uint(v0.y);
                a[mi][1] = __float_as_uint(v1.x);
                a[mi][3] = __float_as_uint(v1.y);
            }
            uint32_t b[4][2];
#pragma unroll
            for (int ni = 0; ni < 4; ni++) {
                int n = warpN + ni * 8 + g8;
                int e = (n << 1) & 6;
                float2 w = *(const float2*)&Bs[n * SROW + kb + ((2 * t4) ^ e)];
                b[ni][0] = __float_as_uint(w.x);
                b[ni][1] = __float_as_uint(w.y);
            }
#pragma unroll
            for (int mi = 0; mi < 4; mi++)
#pragma unroll
                for (int ni = 0; ni < 4; ni++)
                    mma_tf32(d[mi][ni], a[mi], b[ni]);
        }
        __syncthreads();
    }

    // ---- epilogue: scatter-add (sparse) or direct store (dense) ----
#pragma unroll
    for (int mi = 0; mi < 4; mi++) {
        int r0 = mBase + warpM + mi * 16 + g8;
#pragma unroll
        for (int half = 0; half < 2; half++) {
            int rr = r0 + half * 8;
            if (rr >= M) continue;
            size_t orow = out_idx ? (size_t)out_idx[(size_t)k * M + rr] : (size_t)rr;
            float* crow = C + orow * Cout;
#pragma unroll
            for (int ni = 0; ni < 4; ni++) {
                int col = n0 + warpN + ni * 8 + t4 * 2;
                if (col + 1 < Cout) {
                    float v0 = d[mi][ni][half * 2 + 0];
                    float v1 = d[mi][ni][half * 2 + 1];
                    if (out_idx) red_add_v2(crow + col, v0, v1);
                    else        *(float2*)(crow + col) = make_float2(v0, v1);
                }
            }
        }
    }
}

// ===== weight transpose [K][Cin][Cout] -> [K][Cout][Cin], tf32-rounded ====
__global__ void transpose_kernel(const float* __restrict__ in, float* __restrict__ out,
                                 int R, int Ccol)
{
    __shared__ float t[32][33];
    const size_t koff = (size_t)blockIdx.z * R * Ccol;
    const float* ink = in + koff;
    float* outk = out + koff;
    int c0 = blockIdx.x * 32, r0 = blockIdx.y * 32;
    for (int i = threadIdx.y; i < 32; i += 8) {
        int r = r0 + i, c = c0 + threadIdx.x;
        t[i][threadIdx.x] = (r < R && c < Ccol) ? ink[(size_t)r * Ccol + c] : 0.f;
    }
    __syncthreads();
    for (int i = threadIdx.y; i < 32; i += 8) {
        int cc = c0 + i, rr = r0 + threadIdx.x;
        if (cc < Ccol && rr < R) outk[(size_t)cc * R + rr] = to_tf32(t[threadIdx.x][i]);
    }
}

// ======================= tf32 convert (for f3) ===========================
__global__ void cvt_kernel(const float* __restrict__ in, float* __restrict__ out, int n)
{
    int i = blockIdx.x * blockDim.x + threadIdx.x;
    if (i < n) out[i] = to_tf32(in[i]);
}

// ======================= BN kernels ======================================
__global__ void stats_kernel(const float* __restrict__ x, int N, int C,
                             float* __restrict__ sum, float* __restrict__ sq)
{
    extern __shared__ float s[];
    for (int i = threadIdx.x; i < 2 * C; i += blockDim.x) s[i] = 0.f;
    __syncthreads();
    size_t total = (size_t)N * C;
    for (size_t i = (size_t)blockIdx.x * blockDim.x + threadIdx.x; i < total;
         i += (size_t)gridDim.x * blockDim.x) {
        float v = x[i];
        int c = (int)(i % (size_t)C);
        atomicAdd(&s[c], v);
        atomicAdd(&s[C + c], v * v);
    }
    __syncthreads();
    for (int c = threadIdx.x; c < C; c += blockDim.x) {
        atomicAdd(&sum[c], s[c]);
        atomicAdd(&sq[c],  s[C + c]);
    }
}

__global__ void bnparam_kernel(const float* __restrict__ sum, const float* __restrict__ sq,
                               const float* __restrict__ gamma, const float* __restrict__ beta,
                               int N, int C,
                               float* __restrict__ scale, float* __restrict__ shift)
{
    int c = blockIdx.x * blockDim.x + threadIdx.x;
    if (c < C) {
        float invN = 1.f / (float)N;
        float m = sum[c] * invN;
        float v = sq[c] * invN - m * m;
        float sc = gamma[c] * rsqrtf(v + BN_EPS);
        scale[c] = sc;
        shift[c] = beta[c] - m * sc;
    }
}

// do_cvt: round output to tf32 (it feeds a GEMM next). Final layer: 0.
__global__ void bnapply_kernel(const float* __restrict__ x, int N, int C, int ostride,
                               const float* __restrict__ scale, const float* __restrict__ shift,
                               float* __restrict__ out, int do_cvt)
{
    size_t total = (size_t)N * C;
    for (size_t i = (size_t)blockIdx.x * blockDim.x + threadIdx.x; i < total;
         i += (size_t)gridDim.x * blockDim.x) {
        int c = (int)(i % (size_t)C);
        size_t r = i / (size_t)C;
        float v = fmaxf(fmaf(x[i], scale[c], shift[c]), 0.f);
        out[r * (size_t)ostride + c] = do_cvt ? to_tf32(v) : v;
    }
}

__global__ void copyskip_kernel(const float* __restrict__ f, int N, int Cf,
                                int ostride, int coff, float* __restrict__ out)
{
    size_t total = (size_t)N * Cf;
    for (size_t i = (size_t)blockIdx.x * blockDim.x + threadIdx.x; i < total;
         i += (size_t)gridDim.x * blockDim.x) {
        int c = (int)(i % (size_t)Cf);
        size_t r = i / (size_t)Cf;
        out[r * (size_t)ostride + coff + c] = to_tf32(f[i]);
    }
}

// ==========================================================================
extern "C" void kernel_launch(void* const* d_in, const int* in_sizes, int n_in,
                              void* d_out, int out_size)
{
    (void)in_sizes; (void)n_in; (void)out_size;

    const float* f0    = (const float*)d_in[0];
    const float* f1    = (const float*)d_in[1];
    const float* f2    = (const float*)d_in[2];
    const float* f3    = (const float*)d_in[3];
    const float* W_up2 = (const float*)d_in[4];
    const float* W_up1 = (const float*)d_in[5];
    const float* W_up0 = (const float*)d_in[6];
    const float* W_s0  = (const float*)d_in[7];
    const float* W_s1  = (const float*)d_in[8];
    const float* W_s2  = (const float*)d_in[9];
    const float* g_up2 = (const float*)d_in[10]; const float* b_up2 = (const float*)d_in[11];
    const float* g_up1 = (const float*)d_in[12]; const float* b_up1 = (const float*)d_in[13];
    const float* g_up0 = (const float*)d_in[14]; const float* b_up0 = (const float*)d_in[15];
    const float* g_s0  = (const float*)d_in[16]; const float* b_s0  = (const float*)d_in[17];
    const float* g_s1  = (const float*)d_in[18]; const float* b_s1  = (const float*)d_in[19];
    const float* g_s2  = (const float*)d_in[20]; const float* b_s2  = (const float*)d_in[21];
    const int* up2_in = (const int*)d_in[22]; const int* up2_out = (const int*)d_in[23];
    const int* up1_in = (const int*)d_in[24]; const int* up1_out = (const int*)d_in[25];
    const int* up0_in = (const int*)d_in[26]; const int* up0_out = (const int*)d_in[27];
    const int* sm0_in = (const int*)d_in[28]; const int* sm0_out = (const int*)d_in[29];
    const int* sm1_in = (const int*)d_in[30]; const int* sm1_out = (const int*)d_in[31];

    float *acc, *bufA, *bufB, *wt, *sum, *sq, *scale, *shift;
    cudaGetSymbolAddress((void**)&acc,   g_acc);
    cudaGetSymbolAddress((void**)&bufA,  g_bufA);
    cudaGetSymbolAddress((void**)&bufB,  g_bufB);
    cudaGetSymbolAddress((void**)&wt,    g_wt);
    cudaGetSymbolAddress((void**)&sum,   g_sum);
    cudaGetSymbolAddress((void**)&sq,    g_sq);
    cudaGetSymbolAddress((void**)&scale, g_scale);
    cudaGetSymbolAddress((void**)&shift, g_shift);

    const int N0 = 30000, N1 = 12000, N2 = 5000;
    const int K = 27;

    // --- transpose all weights into pool (tf32-rounded) ---
    float* wt_up2 = wt;
    float* wt_up1 = wt_up2 + (size_t)27 * 128 * 128;
    float* wt_up0 = wt_up1 + (size_t)27 * 192 * 192;
    float* wt_s0  = wt_up0 + (size_t)27 * 224 * 224;
    float* wt_s1  = wt_s0  + (size_t)27 * 240 * 512;
    float* wt_s2  = wt_s1  + (size_t)27 * 512 * 512;

    auto tlaunch = [&](const float* W, float* WT, int Cin, int Cout, int kk) {
        dim3 tg((Cout + 31) / 32, (Cin + 31) / 32, kk);
        transpose_kernel<<<tg, dim3(32, 8), 0, 0>>>(W, WT, Cin, Cout);
    };
    tlaunch(W_up2, wt_up2, 128, 128, K);
    tlaunch(W_up1, wt_up1, 192, 192, K);
    tlaunch(W_up0, wt_up0, 224, 224, K);
    tlaunch(W_s0,  wt_s0,  240, 512, K);
    tlaunch(W_s1,  wt_s1,  512, 512, K);
    tlaunch(W_s2,  wt_s2,  512, 512, 1);

    // f3 -> tf32 copy in bufB (bufB not used until up1's output)
    cvt_kernel<<<(2000 * 128 + 255) / 256, 256, 0, 0>>>(f3, bufB, 2000 * 128);

    auto layer = [&](const float* A, const float* WT,
                     const int* ii, const int* oi,
                     int M, int Cin, int Cout, int Nout,
                     const float* gamma, const float* beta,
                     float* outbuf, int ostride,
                     const float* skip, int Cskip, int skip_N, int do_cvt)
    {
        bool sparse = (oi != nullptr);
        float* dst = sparse ? acc : outbuf;   // dense final layer stores direct
        if (sparse)
            cudaMemsetAsync(acc, 0, (size_t)Nout * Cout * sizeof(float), 0);
        cudaMemsetAsync(sum, 0, Cout * sizeof(float), 0);
        cudaMemsetAsync(sq,  0, Cout * sizeof(float), 0);

        dim3 grid((M + 127) / 128, (Cout + 127) / 128, sparse ? K : 1);
        mma_gs_kernel<<<grid, 256, 0, 0>>>(A, WT, ii, oi, dst, M, Cin, Cout);

        stats_kernel<<<592, 256, 2 * Cout * sizeof(float), 0>>>(dst, Nout, Cout, sum, sq);
        bnparam_kernel<<<2, 256, 0, 0>>>(sum, sq, gamma, beta, Nout, Cout, scale, shift);
        bnapply_kernel<<<592, 256, 0, 0>>>(dst, Nout, Cout, ostride, scale, shift, outbuf, do_cvt);
        if (skip)
            copyskip_kernel<<<256, 256, 0, 0>>>(skip, skip_N, Cskip, ostride, Cout, outbuf);
    };

    // up2: tf32(f3) -> N2 (Cout 128), concat f2(64) -> bufA[5000,192]
    layer(bufB, wt_up2, up2_in, up2_out, 1600, 128, 128, N2, g_up2, b_up2, bufA, 192, f2, 64, N2, 1);
    // up1: bufA -> N1 (Cout 192), concat f1(32) -> bufB[12000,224]
    layer(bufA, wt_up1, up1_in, up1_out, 4000, 192, 192, N1, g_up1, b_up1, bufB, 224, f1, 32, N1, 1);
    // up0: bufB -> N0 (Cout 224), concat f0(16) -> bufA[30000,240]
    layer(bufB, wt_up0, up0_in, up0_out, 10000, 224, 224, N0, g_up0, b_up0, bufA, 240, f0, 16, N0, 1);
    // s0: bufA[30000,240] -> N0 (Cout 512) -> bufB
    layer(bufA, wt_s0, sm0_in, sm0_out, 10000, 240, 512, N0, g_s0, b_s0, bufB, 512, nullptr, 0, 0, 1);
    // s1: bufB -> N0 (Cout 512) -> bufA
    layer(bufB, wt_s1, sm1_in, sm1_out, 10000, 512, 512, N0, g_s1, b_s1, bufA, 512, nullptr, 0, 0, 1);
    // s2: dense GEMM bufA @ W_s2 -> d_out (fp32 output, no cvt)
    layer(bufA, wt_s2, nullptr, nullptr, N0, 512, 512, N0, g_s2, b_s2, (float*)d_out, 512, nullptr, 0, 0, 0);
}

// round 9
// speedup vs baseline: 1.1590x; 1.1590x over previous
#include <cuda_runtime.h>
#include <cuda_bf16.h>
#include <cstdint>
#include <cstddef>

#define BN_EPS 1e-5f
#define SROW 40      // A smem row stride (floats), interleaved-swizzle layout
#define BROW 36      // B smem row stride (floats), linear layout (16B-aligned rows)

// dynamic smem layout (bytes):
//   [0, 512)                 rowIdx (128 ints)
//   [512, 512+40960)         As: 2 buffers x 128 x SROW floats
//   [41472, 41472+36864)     Bs: 2 buffers x 128 x BROW floats
#define OFF_AS 512
#define OFF_BS 41472
#define SMEM_DYN (512 + 2*128*SROW*4 + 2*128*BROW*4)

// ======================= static scratch (no allocs) =======================
__device__ float g_acc [30000 * 512];
__device__ float g_bufA[30000 * 512];
__device__ float g_bufB[30000 * 512];
__device__ float g_wt  [13450240];      // transposed tf32 weights pool
__device__ float g_sum [512];
__device__ float g_sq  [512];
__device__ float g_scale[512];
__device__ float g_shift[512];

// ======================= helpers =========================================
__device__ __forceinline__ float to_tf32(float x) {
    float y;
    asm("cvt.rna.tf32.f32 %0, %1;" : "=f"(y) : "f"(x));
    return y;
}
__device__ __forceinline__ uint32_t smem_u32(const void* p) {
    uint32_t a;
    asm("{ .reg .u64 t; cvta.to.shared.u64 t, %1; cvt.u32.u64 %0, t; }" : "=r"(a) : "l"(p));
    return a;
}
__device__ __forceinline__ void mma_tf32(float* d, const uint32_t* a, const uint32_t* b) {
    asm volatile(
        "mma.sync.aligned.m16n8k8.row.col.f32.tf32.tf32.f32 "
        "{%0,%1,%2,%3}, {%4,%5,%6,%7}, {%8,%9}, {%0,%1,%2,%3};"
        : "+f"(d[0]), "+f"(d[1]), "+f"(d[2]), "+f"(d[3])
        : "r"(a[0]), "r"(a[1]), "r"(a[2]), "r"(a[3]), "r"(b[0]), "r"(b[1]));
}
__device__ __forceinline__ void red_add_v2(float* p, float a, float b) {
    asm volatile("red.global.add.v2.f32 [%0], {%1, %2};"
                 :: "l"(p), "f"(a), "f"(b) : "memory");
}
__device__ __forceinline__ void cp_async16(uint32_t dst, const void* src, int szvalid) {
    asm volatile("cp.async.cg.shared.global [%0], [%1], 16, %2;"
                 :: "r"(dst), "l"(src), "r"(szvalid) : "memory");
}
#define CP_COMMIT()  asm volatile("cp.async.commit_group;" ::: "memory")
#define CP_WAIT(n)   asm volatile("cp.async.wait_group %0;" :: "n"(n) : "memory")

// ======================= tensor-core gather-GEMM-scatter ==================
// CTA: 256 thr (8 warps 2x4), tile 128(M) x 128(N), K-chunks of 32.
// A: gathered rows, register-prefetched 1 chunk ahead, stored to interleaved-
//    swizzled smem (conflict-free LDS.64 fragment loads).
// B: cp.async double-buffered into linear smem (row stride 36 floats ->
//    conflict-free LDS.32 fragment loads, zero register cost).
// ONE __syncthreads per chunk. Race-free ordering: cp.async for chunk c+1 is
// issued AFTER barrier c, so every warp has finished the MMA that reads the
// destination buffer (chunk c-1's) before any write lands. CP_WAIT for chunk
// c precedes barrier c, which then publishes the data CTA-wide.
__global__ __launch_bounds__(256, 2) void mma_gs_kernel(
    const float* __restrict__ A, const float* __restrict__ WT,
    const int* __restrict__ in_idx, const int* __restrict__ out_idx,
    float* __restrict__ C, int M, int Cin, int Cout)
{
    extern __shared__ char sm[];
    int*   rowIdx = (int*)sm;
    float* As     = (float*)(sm + OFF_AS);
    float* Bs     = (float*)(sm + OFF_BS);
    const uint32_t bsU = smem_u32(sm) + OFF_BS;

    const int tid  = threadIdx.x;
    const int wid  = tid >> 5;
    const int lane = tid & 31;
    const int g8   = lane >> 2;
    const int t4   = lane & 3;

    const int k     = blockIdx.z;
    const int mBase = blockIdx.x * 128;
    const int n0    = blockIdx.y * 128;
    const float* WTk = WT + (size_t)k * Cout * Cin;

    const int warpM = (wid >> 2) * 64;
    const int warpN = (wid & 3) * 32;

    if (tid < 128) {
        int g = mBase + tid;
        int ri = 0;
        if (g < M) ri = in_idx ? in_idx[(size_t)k * M + g] : g;
        rowIdx[tid] = ri;
    }
    __syncthreads();

    // per-thread A source pointers and B cp.async sources (row, 4j offsets)
    const float* aptr[4];
    const float* bptr[4];
    int bvalidrow[4];
#pragma unroll
    for (int s = 0; s < 4; ++s) {
        int gi = tid + s * 256;
        int row = gi >> 3, j = gi & 7;
        aptr[s] = A + (size_t)rowIdx[row] * Cin + 4 * j;
        int brow = n0 + row;
        bvalidrow[s] = (brow < Cout);
        bptr[s] = WTk + (size_t)(bvalidrow[s] ? brow : 0) * Cin + 4 * j;
    }

    float d[4][4][4];
#pragma unroll
    for (int mi = 0; mi < 4; mi++)
#pragma unroll
        for (int ni = 0; ni < 4; ni++)
#pragma unroll
            for (int r = 0; r < 4; r++) d[mi][ni][r] = 0.f;

    const int nc = (Cin + 31) >> 5;

    // ---- prologue: A chunk 0 -> regs; B chunk 0 -> cp.async buf0 ----
    float4 pav[4];
#pragma unroll
    for (int s = 0; s < 4; ++s) {
        int j = (tid + s * 256) & 7;
        int col = 4 * j;
        pav[s] = make_float4(0.f, 0.f, 0.f, 0.f);
        if (col < Cin) pav[s] = *(const float4*)(aptr[s]);
    }
#pragma unroll
    for (int s = 0; s < 4; ++s) {
        int gi = tid + s * 256;
        int row = gi >> 3, j = gi & 7;
        int col = 4 * j;
        int ok = (col < Cin && bvalidrow[s]) ? 16 : 0;
        cp_async16(bsU + (uint32_t)(row * BROW + 4 * j) * 4, bptr[s], ok);
    }
    CP_COMMIT();

    for (int c = 0; c < nc; ++c) {
        const int st = c & 1;

        // ---- store prefetched A chunk c into As[st] (swizzled) ----
        float* AsBuf = As + st * 128 * SROW;
#pragma unroll
        for (int s = 0; s < 4; ++s) {
            int gi  = tid + s * 256;
            int row = gi >> 3, j = gi & 7;
            int e    = (row << 1) & 6;
            int base = row * SROW + (j >> 1) * 8;
            int o    = j & 1;
            AsBuf[base + ((0 + o) ^ e)] = pav[s].x;
            AsBuf[base + ((2 + o) ^ e)] = pav[s].y;
            AsBuf[base + ((4 + o) ^ e)] = pav[s].z;
            AsBuf[base + ((6 + o) ^ e)] = pav[s].w;
        }

        // ---- prefetch A chunk c+1 into registers ----
        if (c + 1 < nc) {
            const int c1 = (c + 1) << 5;
#pragma unroll
            for (int s = 0; s < 4; ++s) {
                int j = (tid + s * 256) & 7;
                int col = c1 + 4 * j;
                pav[s] = make_float4(0.f, 0.f, 0.f, 0.f);
                if (col < Cin) pav[s] = *(const float4*)(aptr[s] + c1);
            }
        }

        // ---- complete B chunk c, publish everything CTA-wide ----
        CP_WAIT(0);
        __syncthreads();

        // ---- NOW safe to issue B chunk c+1 into buffer st^1:
        //      all warps finished the MMA (chunk c-1) that read it ----
        if (c + 1 < nc) {
            const int c1 = (c + 1) << 5;
#pragma unroll
            for (int s = 0; s < 4; ++s) {
                int gi = tid + s * 256;
                int row = gi >> 3, j = gi & 7;
                int col = c1 + 4 * j;
                int ok = (col < Cin && bvalidrow[s]) ? 16 : 0;
                cp_async16(bsU + (uint32_t)((st ^ 1) * 128 * BROW + row * BROW + 4 * j) * 4,
                           bptr[s] + c1, ok);
            }
            CP_COMMIT();
        }

        // ---- 4 k8 MMA steps (covers chunk c+1's cp.async latency) ----
        const float* BsBuf = Bs + st * 128 * BROW;
#pragma unroll
        for (int kk = 0; kk < 4; ++kk) {
            const int kb = kk << 3;
            uint32_t a[4][4];
#pragma unroll
            for (int mi = 0; mi < 4; mi++) {
                int r = warpM + mi * 16 + g8;
                int e = (r << 1) & 6;
                int off = r * SROW + kb + ((2 * t4) ^ e);
                float2 v0 = *(const float2*)&AsBuf[off];
                float2 v1 = *(const float2*)&AsBuf[off + 8 * SROW];
                a[mi][0] = __float_as_uint(v0.x);
                a[mi][2] = __float_as_uint(v0.y);
                a[mi][1] = __float_as_uint(v1.x);
                a[mi][3] = __float_as_uint(v1.y);
            }
            uint32_t b[4][2];
#pragma unroll
            for (int ni = 0; ni < 4; ni++) {
                int n = warpN + ni * 8 + g8;
                b[ni][0] = __float_as_uint(BsBuf[n * BROW + kb + t4]);
                b[ni][1] = __float_as_uint(BsBuf[n * BROW + kb + t4 + 4]);
            }
#pragma unroll
            for (int mi = 0; mi < 4; mi++)
#pragma unroll
                for (int ni = 0; ni < 4; ni++)
                    mma_tf32(d[mi][ni], a[mi], b[ni]);
        }
        // no trailing barrier: next iteration's A-store hits the other A
        // buffer; B writes are gated behind the next barrier.
    }

    // ---- epilogue: scatter-add (sparse) or direct store (dense) ----
#pragma unroll
    for (int mi = 0; mi < 4; mi++) {
        int r0 = mBase + warpM + mi * 16 + g8;
#pragma unroll
        for (int half = 0; half < 2; half++) {
            int rr = r0 + half * 8;
            if (rr >= M) continue;
            size_t orow = out_idx ? (size_t)out_idx[(size_t)k * M + rr] : (size_t)rr;
            float* crow = C + orow * Cout;
#pragma unroll
            for (int ni = 0; ni < 4; ni++) {
                int col = n0 + warpN + ni * 8 + t4 * 2;
                if (col + 1 < Cout) {
                    float v0 = d[mi][ni][half * 2 + 0];
                    float v1 = d[mi][ni][half * 2 + 1];
                    if (out_idx) red_add_v2(crow + col, v0, v1);
                    else        *(float2*)(crow + col) = make_float2(v0, v1);
                }
            }
        }
    }
}

// ===== weight transpose [K][Cin][Cout] -> [K][Cout][Cin], tf32-rounded ====
__global__ void transpose_kernel(const float* __restrict__ in, float* __restrict__ out,
                                 int R, int Ccol)
{
    __shared__ float t[32][33];
    const size_t koff = (size_t)blockIdx.z * R * Ccol;
    const float* ink = in + koff;
    float* outk = out + koff;
    int c0 = blockIdx.x * 32, r0 = blockIdx.y * 32;
    for (int i = threadIdx.y; i < 32; i += 8) {
        int r = r0 + i, c = c0 + threadIdx.x;
        t[i][threadIdx.x] = (r < R && c < Ccol) ? ink[(size_t)r * Ccol + c] : 0.f;
    }
    __syncthreads();
    for (int i = threadIdx.y; i < 32; i += 8) {
        int cc = c0 + i, rr = r0 + threadIdx.x;
        if (cc < Ccol && rr < R) outk[(size_t)cc * R + rr] = to_tf32(t[threadIdx.x][i]);
    }
}

// ======================= tf32 convert (for f3) ===========================
__global__ void cvt_kernel(const float* __restrict__ in, float* __restrict__ out, int n)
{
    int i = blockIdx.x * blockDim.x + threadIdx.x;
    if (i < n) out[i] = to_tf32(in[i]);
}

// ======================= BN kernels ======================================
__global__ void stats_kernel(const float* __restrict__ x, int N, int C,
                             float* __restrict__ sum, float* __restrict__ sq)
{
    extern __shared__ float s[];
    for (int i = threadIdx.x; i < 2 * C; i += blockDim.x) s[i] = 0.f;
    __syncthreads();
    size_t total = (size_t)N * C;
    for (size_t i = (size_t)blockIdx.x * blockDim.x + threadIdx.x; i < total;
         i += (size_t)gridDim.x * blockDim.x) {
        float v = x[i];
        int c = (int)(i % (size_t)C);
        atomicAdd(&s[c], v);
        atomicAdd(&s[C + c], v * v);
    }
    __syncthreads();
    for (int c = threadIdx.x; c < C; c += blockDim.x) {
        atomicAdd(&sum[c], s[c]);
        atomicAdd(&sq[c],  s[C + c]);
    }
}

__global__ void bnparam_kernel(const float* __restrict__ sum, const float* __restrict__ sq,
                               const float* __restrict__ gamma, const float* __restrict__ beta,
                               int N, int C,
                               float* __restrict__ scale, float* __restrict__ shift)
{
    int c = blockIdx.x * blockDim.x + threadIdx.x;
    if (c < C) {
        float invN = 1.f / (float)N;
        float m = sum[c] * invN;
        float v = sq[c] * invN - m * m;
        float sc = gamma[c] * rsqrtf(v + BN_EPS);
        scale[c] = sc;
        shift[c] = beta[c] - m * sc;
    }
}

// do_cvt: round output to tf32 (it feeds a GEMM next). Final layer: 0.
__global__ void bnapply_kernel(const float* __restrict__ x, int N, int C, int ostride,
                               const float* __restrict__ scale, const float* __restrict__ shift,
                               float* __restrict__ out, int do_cvt)
{
    size_t total = (size_t)N * C;
    for (size_t i = (size_t)blockIdx.x * blockDim.x + threadIdx.x; i < total;
         i += (size_t)gridDim.x * blockDim.x) {
        int c = (int)(i % (size_t)C);
        size_t r = i / (size_t)C;
        float v = fmaxf(fmaf(x[i], scale[c], shift[c]), 0.f);
        out[r * (size_t)ostride + c] = do_cvt ? to_tf32(v) : v;
    }
}

__global__ void copyskip_kernel(const float* __restrict__ f, int N, int Cf,
                                int ostride, int coff, float* __restrict__ out)
{
    size_t total = (size_t)N * Cf;
    for (size_t i = (size_t)blockIdx.x * blockDim.x + threadIdx.x; i < total;
         i += (size_t)gridDim.x * blockDim.x) {
        int c = (int)(i % (size_t)Cf);
        size_t r = i / (size_t)Cf;
        out[r * (size_t)ostride + coff + c] = to_tf32(f[i]);
    }
}

// ==========================================================================
extern "C" void kernel_launch(void* const* d_in, const int* in_sizes, int n_in,
                              void* d_out, int out_size)
{
    (void)in_sizes; (void)n_in; (void)out_size;

    const float* f0    = (const float*)d_in[0];
    const float* f1    = (const float*)d_in[1];
    const float* f2    = (const float*)d_in[2];
    const float* f3    = (const float*)d_in[3];
    const float* W_up2 = (const float*)d_in[4];
    const float* W_up1 = (const float*)d_in[5];
    const float* W_up0 = (const float*)d_in[6];
    const float* W_s0  = (const float*)d_in[7];
    const float* W_s1  = (const float*)d_in[8];
    const float* W_s2  = (const float*)d_in[9];
    const float* g_up2 = (const float*)d_in[10]; const float* b_up2 = (const float*)d_in[11];
    const float* g_up1 = (const float*)d_in[12]; const float* b_up1 = (const float*)d_in[13];
    const float* g_up0 = (const float*)d_in[14]; const float* b_up0 = (const float*)d_in[15];
    const float* g_s0  = (const float*)d_in[16]; const float* b_s0  = (const float*)d_in[17];
    const float* g_s1  = (const float*)d_in[18]; const float* b_s1  = (const float*)d_in[19];
    const float* g_s2  = (const float*)d_in[20]; const float* b_s2  = (const float*)d_in[21];
    const int* up2_in = (const int*)d_in[22]; const int* up2_out = (const int*)d_in[23];
    const int* up1_in = (const int*)d_in[24]; const int* up1_out = (const int*)d_in[25];
    const int* up0_in = (const int*)d_in[26]; const int* up0_out = (const int*)d_in[27];
    const int* sm0_in = (const int*)d_in[28]; const int* sm0_out = (const int*)d_in[29];
    const int* sm1_in = (const int*)d_in[30]; const int* sm1_out = (const int*)d_in[31];

    float *acc, *bufA, *bufB, *wt, *sum, *sq, *scale, *shift;
    cudaGetSymbolAddress((void**)&acc,   g_acc);
    cudaGetSymbolAddress((void**)&bufA,  g_bufA);
    cudaGetSymbolAddress((void**)&bufB,  g_bufB);
    cudaGetSymbolAddress((void**)&wt,    g_wt);
    cudaGetSymbolAddress((void**)&sum,   g_sum);
    cudaGetSymbolAddress((void**)&sq,    g_sq);
    cudaGetSymbolAddress((void**)&scale, g_scale);
    cudaGetSymbolAddress((void**)&shift, g_shift);

    cudaFuncSetAttribute(mma_gs_kernel,
                         cudaFuncAttributeMaxDynamicSharedMemorySize, SMEM_DYN);

    const int N0 = 30000, N1 = 12000, N2 = 5000;
    const int K = 27;

    // --- transpose all weights into pool (tf32-rounded) ---
    float* wt_up2 = wt;
    float* wt_up1 = wt_up2 + (size_t)27 * 128 * 128;
    float* wt_up0 = wt_up1 + (size_t)27 * 192 * 192;
    float* wt_s0  = wt_up0 + (size_t)27 * 224 * 224;
    float* wt_s1  = wt_s0  + (size_t)27 * 240 * 512;
    float* wt_s2  = wt_s1  + (size_t)27 * 512 * 512;

    auto tlaunch = [&](const float* W, float* WT, int Cin, int Cout, int kk) {
        dim3 tg((Cout + 31) / 32, (Cin + 31) / 32, kk);
        transpose_kernel<<<tg, dim3(32, 8), 0, 0>>>(W, WT, Cin, Cout);
    };
    tlaunch(W_up2, wt_up2, 128, 128, K);
    tlaunch(W_up1, wt_up1, 192, 192, K);
    tlaunch(W_up0, wt_up0, 224, 224, K);
    tlaunch(W_s0,  wt_s0,  240, 512, K);
    tlaunch(W_s1,  wt_s1,  512, 512, K);
    tlaunch(W_s2,  wt_s2,  512, 512, 1);

    // f3 -> tf32 copy in bufB (bufB not used until up1's output)
    cvt_kernel<<<(2000 * 128 + 255) / 256, 256, 0, 0>>>(f3, bufB, 2000 * 128);

    auto layer = [&](const float* A, const float* WT,
                     const int* ii, const int* oi,
                     int M, int Cin, int Cout, int Nout,
                     const float* gamma, const float* beta,
                     float* outbuf, int ostride,
                     const float* skip, int Cskip, int skip_N, int do_cvt)
    {
        bool sparse = (oi != nullptr);
        float* dst = sparse ? acc : outbuf;   // dense final layer stores direct
        if (sparse)
            cudaMemsetAsync(acc, 0, (size_t)Nout * Cout * sizeof(float), 0);
        cudaMemsetAsync(sum, 0, Cout * sizeof(float), 0);
        cudaMemsetAsync(sq,  0, Cout * sizeof(float), 0);

        dim3 grid((M + 127) / 128, (Cout + 127) / 128, sparse ? K : 1);
        mma_gs_kernel<<<grid, 256, SMEM_DYN, 0>>>(A, WT, ii, oi, dst, M, Cin, Cout);

        stats_kernel<<<592, 256, 2 * Cout * sizeof(float), 0>>>(dst, Nout, Cout, sum, sq);
        bnparam_kernel<<<2, 256, 0, 0>>>(sum, sq, gamma, beta, Nout, Cout, scale, shift);
        bnapply_kernel<<<592, 256, 0, 0>>>(dst, Nout, Cout, ostride, scale, shift, outbuf, do_cvt);
        if (skip)
            copyskip_kernel<<<256, 256, 0, 0>>>(skip, skip_N, Cskip, ostride, Cout, outbuf);
    };

    // up2: tf32(f3) -> N2 (Cout 128), concat f2(64) -> bufA[5000,192]
    layer(bufB, wt_up2, up2_in, up2_out, 1600, 128, 128, N2, g_up2, b_up2, bufA, 192, f2, 64, N2, 1);
    // up1: bufA -> N1 (Cout 192), concat f1(32) -> bufB[12000,224]
    layer(bufA, wt_up1, up1_in, up1_out, 4000, 192, 192, N1, g_up1, b_up1, bufB, 224, f1, 32, N1, 1);
    // up0: bufB -> N0 (Cout 224), concat f0(16) -> bufA[30000,240]
    layer(bufB, wt_up0, up0_in, up0_out, 10000, 224, 224, N0, g_up0, b_up0, bufA, 240, f0, 16, N0, 1);
    // s0: bufA[30000,240] -> N0 (Cout 512) -> bufB
    layer(bufA, wt_s0, sm0_in, sm0_out, 10000, 240, 512, N0, g_s0, b_s0, bufB, 512, nullptr, 0, 0, 1);
    // s1: bufB -> N0 (Cout 512) -> bufA
    layer(bufB, wt_s1, sm1_in, sm1_out, 10000, 512, 512, N0, g_s1, b_s1, bufA, 512, nullptr, 0, 0, 1);
    // s2: dense GEMM bufA @ W_s2 -> d_out (fp32 output, no cvt)
    layer(bufA, wt_s2, nullptr, nullptr, N0, 512, 512, N0, g_s2, b_s2, (float*)d_out, 512, nullptr, 0, 0, 0);
}